// round 10
// baseline (speedup 1.0000x reference)
#include <cuda_runtime.h>
#include <cuda_bf16.h>
#include <cstdint>

// Problem constants
#define NUM_QT   65
#define NUM_OT   151
#define PAIR_NUM 90
#define BATCH    8192
#define BOX      10
#define TOTAL_ELEMS (NUM_QT * PAIR_NUM * NUM_OT * NUM_OT)  // 133,385,850
#define N4_TOTAL (TOTAL_ELEMS / 4)                         // 33,346,462 (tail = 2)

// ---------------------------------------------------------------------------
// SM copy of float4 range [c4_lo, c4_hi), plus the 2-element scalar tail.
// Simple grid-stride (best measured SM bandwidth, ~6.3 TB/s).
// ---------------------------------------------------------------------------
__global__ void __launch_bounds__(256) copy_range_kernel(
    const float4* __restrict__ src4,
    float4* __restrict__ dst4,
    const float* __restrict__ src,
    float* __restrict__ dst,
    int c4_lo, int c4_hi)
{
    const int stride = gridDim.x * blockDim.x;
    for (int i = c4_lo + blockIdx.x * blockDim.x + threadIdx.x; i < c4_hi; i += stride) {
        dst4[i] = src4[i];
    }
    // Scalar tail (TOTAL_ELEMS - 4*N4_TOTAL = 2 elements)
    if (blockIdx.x == 0 && threadIdx.x < (TOTAL_ELEMS - 4 * N4_TOTAL)) {
        int e = 4 * N4_TOTAL + threadIdx.x;
        dst[e] = src[e];
    }
}

// ---------------------------------------------------------------------------
// Scatter-add attention products (full range).
// One thread per (batch, pair). pair p -> i = p/9, j' = p%9, j = j' + (j' >= i).
// out[qt[b]][p][label[b,j]][label[b,i]] += att[b,i]*att[b,j]
// atomicAdd result unused -> REDG (fire-and-forget).
// ---------------------------------------------------------------------------
__global__ void __launch_bounds__(256) scatter_kernel(
    const int* __restrict__ obj_label,
    const int* __restrict__ qus_type,
    const float* __restrict__ attention,
    float* __restrict__ out)
{
    int idx = blockIdx.x * blockDim.x + threadIdx.x;
    if (idx >= BATCH * PAIR_NUM) return;

    int b = idx / PAIR_NUM;
    int p = idx - b * PAIR_NUM;
    int i = p / (BOX - 1);
    int jr = p - i * (BOX - 1);
    int j = jr + (jr >= i ? 1 : 0);

    int qt  = __ldg(&qus_type[b]);
    int oli = __ldg(&obj_label[b * BOX + i]);
    int olj = __ldg(&obj_label[b * BOX + j]);
    float ai = __ldg(&attention[b * BOX + i]);
    float aj = __ldg(&attention[b * BOX + j]);

    long long off = ((long long)(qt * PAIR_NUM + p) * NUM_OT + olj) * NUM_OT + oli;
    atomicAdd(out + off, ai * aj);
}

// ---------------------------------------------------------------------------
// Launch: concurrent dual-path copy.
//   side stream: copy-engine memcpy of the front ~32% (DMA path, ~3.0 TB/s)
//   stream 0:    SM kernel copy of the back ~68%     (SM path,  ~6.3 TB/s)
// If the paths are additive at the HBM controller, effective copy bandwidth
// approaches the 8 TB/s HBM roof. Scatter runs after both complete.
//
// Inputs (metadata order):
//   d_in[0] = obj_label    int32   [8192,10]
//   d_in[1] = qus_type     int32   [8192]
//   d_in[2] = attention    float32 [8192,10]
//   d_in[3] = score_matrix float32 [65,90,151,151]
// ---------------------------------------------------------------------------
extern "C" void kernel_launch(void* const* d_in, const int* in_sizes, int n_in,
                              void* d_out, int out_size)
{
    const int*   obj_label = (const int*)d_in[0];
    const int*   qus_type  = (const int*)d_in[1];
    const float* attention = (const float*)d_in[2];
    const float* score     = (const float*)d_in[3];
    float*       out       = (float*)d_out;

    // Lazy one-time resource setup (first call = uncaptured correctness run).
    static cudaStream_t s_side = nullptr;
    static cudaEvent_t  ev_fork = nullptr, ev_ce = nullptr;
    if (s_side == nullptr) {
        cudaStreamCreateWithFlags(&s_side, cudaStreamNonBlocking);
        cudaEventCreateWithFlags(&ev_fork, cudaEventDisableTiming);
        cudaEventCreateWithFlags(&ev_ce, cudaEventDisableTiming);
    }

    // Split: CE takes front 32% (float4-aligned), SM takes the rest.
    const int c4_split = (int)(((long long)N4_TOTAL * 32) / 100);
    const size_t ce_bytes = (size_t)c4_split * sizeof(float4);

    // Fork side stream off the capture origin stream.
    cudaEventRecord(ev_fork, 0);
    cudaStreamWaitEvent(s_side, ev_fork, 0);

    // Copy engine: front portion on side stream (concurrent with SM copy).
    cudaMemcpyAsync(out, score, ce_bytes, cudaMemcpyDeviceToDevice, s_side);
    cudaEventRecord(ev_ce, s_side);

    // SM copy: back portion + tail on stream 0.
    {
        int threads = 256;
        int blocks = 148 * 16;
        copy_range_kernel<<<blocks, threads, 0, 0>>>(
            (const float4*)score, (float4*)out, score, out, c4_split, N4_TOTAL);
    }

    // Join: stream 0 waits for the CE copy, then scatter sees the full copy.
    cudaStreamWaitEvent(0, ev_ce, 0);

    {
        int total = BATCH * PAIR_NUM;  // 737,280
        int threads = 256;
        int blocks = (total + threads - 1) / threads;
        scatter_kernel<<<blocks, threads, 0, 0>>>(obj_label, qus_type, attention, out);
    }
}

// round 12
// speedup vs baseline: 1.3171x; 1.3171x over previous
#include <cuda_runtime.h>
#include <cuda_bf16.h>
#include <cstdint>

// Problem constants
#define NUM_QT   65
#define NUM_OT   151
#define PAIR_NUM 90
#define BATCH    8192
#define BOX      10
#define TOTAL_ELEMS (NUM_QT * PAIR_NUM * NUM_OT * NUM_OT)  // 133,385,850
#define N4_TOTAL (TOTAL_ELEMS / 4)                         // 33,346,462 (tail = 2)

// ---------------------------------------------------------------------------
// Kernel 1: grid-stride float4 copy score_matrix -> out (proven-best form:
// simple loop, ptxas front-batches loads itself; 2368 blocks x 256).
// ---------------------------------------------------------------------------
__global__ void __launch_bounds__(256) copy_kernel(
    const float4* __restrict__ src4,
    float4* __restrict__ dst4,
    const float* __restrict__ src,
    float* __restrict__ dst)
{
    const int stride = gridDim.x * blockDim.x;
    for (int i = blockIdx.x * blockDim.x + threadIdx.x; i < N4_TOTAL; i += stride) {
        dst4[i] = src4[i];
    }
    // Scalar tail (TOTAL_ELEMS - 4*N4_TOTAL = 2 elements)
    if (blockIdx.x == 0 && threadIdx.x < (TOTAL_ELEMS - 4 * N4_TOTAL)) {
        int e = 4 * N4_TOTAL + threadIdx.x;
        dst[e] = src[e];
    }
}

// ---------------------------------------------------------------------------
// Kernel 2: scatter-add attention products.
// One thread per (batch, pair). pair p -> i = p/9, j' = p%9, j = j' + (j' >= i).
// out[qt[b]][p][label[b,j]][label[b,i]] += att[b,i]*att[b,j]
// Offset fits in int32 (max 133,385,849 < 2^31) -> short address chain.
// atomicAdd result unused -> REDG (fire-and-forget).
// ---------------------------------------------------------------------------
__global__ void __launch_bounds__(256) scatter_kernel(
    const int* __restrict__ obj_label,
    const int* __restrict__ qus_type,
    const float* __restrict__ attention,
    float* __restrict__ out)
{
    int idx = blockIdx.x * blockDim.x + threadIdx.x;
    if (idx >= BATCH * PAIR_NUM) return;

    int b = idx / PAIR_NUM;
    int p = idx - b * PAIR_NUM;
    int i = p / (BOX - 1);
    int jr = p - i * (BOX - 1);
    int j = jr + (jr >= i ? 1 : 0);

    int qt  = __ldg(&qus_type[b]);
    int oli = __ldg(&obj_label[b * BOX + i]);
    int olj = __ldg(&obj_label[b * BOX + j]);
    float ai = __ldg(&attention[b * BOX + i]);
    float aj = __ldg(&attention[b * BOX + j]);

    // offset = ((qt*PAIR + p)*NUM_OT + ol1)*NUM_OT + ol2, ol1=label[j], ol2=label[i]
    int off = ((qt * PAIR_NUM + p) * NUM_OT + olj) * NUM_OT + oli;
    atomicAdd(out + off, ai * aj);
}

// ---------------------------------------------------------------------------
// Launch: serial copy then scatter (measured optimum; all overlap/CE/chunking
// variants regressed — bandwidth-floor bound).
//
// Inputs (metadata order):
//   d_in[0] = obj_label    int32   [8192,10]
//   d_in[1] = qus_type     int32   [8192]
//   d_in[2] = attention    float32 [8192,10]
//   d_in[3] = score_matrix float32 [65,90,151,151]
// ---------------------------------------------------------------------------
extern "C" void kernel_launch(void* const* d_in, const int* in_sizes, int n_in,
                              void* d_out, int out_size)
{
    const int*   obj_label = (const int*)d_in[0];
    const int*   qus_type  = (const int*)d_in[1];
    const float* attention = (const float*)d_in[2];
    const float* score     = (const float*)d_in[3];
    float*       out       = (float*)d_out;

    // Copy: 2368 blocks x 256 threads (best measured: ~6.3 TB/s).
    copy_kernel<<<148 * 16, 256>>>((const float4*)score, (float4*)out, score, out);

    // Scatter: 737,280 updates.
    {
        int total = BATCH * PAIR_NUM;
        int threads = 256;
        int blocks = (total + threads - 1) / threads;
        scatter_kernel<<<blocks, threads>>>(obj_label, qus_type, attention, out);
    }
}